// round 14
// baseline (speedup 1.0000x reference)
#include <cuda_runtime.h>
#include <math.h>
#include <cstdint>

#define BB    2048
#define NN    62
#define FIN   128
#define HID   512
#define HEADS 8
#define FOUT  64
#define NROWS (BB * NN)   // 126976

__device__ float g_hx[(size_t)NROWS * HID];
__device__ float g_h [(size_t)NROWS * HID];
__device__ float g_cs[HID];
// packed weights: smem-image layout [tile][stage][g][c][t] of float2 pairs
__device__ float2 g_Wp2[3 * 4 * 16 * 4 * 128 * 4];   // GAT W, 3 layers
__device__ float2 g_Wp1[4 * 4 * 4 * 128 * 4];        // W_mlp

// ===========================================================================
// helpers
// ===========================================================================
__device__ __forceinline__ uint32_t smem_u32(const void* p) {
    uint32_t a;
    asm("{ .reg .u64 t; cvta.to.shared.u64 t, %1; cvt.u32.u64 %0, t; }"
        : "=r"(a) : "l"(p));
    return a;
}
__device__ __forceinline__ float tf32r(float x) {
    uint32_t u;
    asm("cvt.rna.tf32.f32 %0, %1;" : "=r"(u) : "f"(x));
    return __uint_as_float(u);
}
__device__ __forceinline__ uint32_t tf32u(float x) {
    uint32_t u;
    asm("cvt.rna.tf32.f32 %0, %1;" : "=r"(u) : "f"(x));
    return u;
}
__device__ __forceinline__ void cp_async16(uint32_t dst, const void* src) {
    asm volatile("cp.async.cg.shared.global [%0], [%1], 16;"
                 :: "r"(dst), "l"(src) : "memory");
}
__device__ __forceinline__ void cp_commit() {
    asm volatile("cp.async.commit_group;" ::: "memory");
}
template <int N>
__device__ __forceinline__ void cp_wait() {
    asm volatile("cp.async.wait_group %0;" :: "n"(N) : "memory");
}
__device__ __forceinline__ void mma_tf32(float* c, const uint32_t* a, const uint32_t* b) {
    asm volatile(
        "mma.sync.aligned.m16n8k8.row.col.f32.tf32.tf32.f32 "
        "{%0,%1,%2,%3}, {%4,%5,%6,%7}, {%8,%9}, {%0,%1,%2,%3};"
        : "+f"(c[0]), "+f"(c[1]), "+f"(c[2]), "+f"(c[3])
        : "r"(a[0]), "r"(a[1]), "r"(a[2]), "r"(a[3]), "r"(b[0]), "r"(b[1]));
}

// ===========================================================================
// K0: weight packing (one-time)
// ===========================================================================
__global__ void k0_pack_w2(const float* __restrict__ Wg) {
    int idx = blockIdx.x * 256 + threadIdx.x;     // [3][4][16][4][128][4]
    if (idx >= 3 * 4 * 16 * 4 * 128 * 4) return;
    int t    = idx & 3;
    int c    = (idx >> 2) & 127;
    int g    = (idx >> 9) & 3;
    int s    = (idx >> 11) & 15;
    int tile = (idx >> 15) & 3;
    int l    = idx >> 17;
    int col  = tile * 128 + c;
    int head = col >> 6, d = col & 63;
    int k    = s * 32 + g * 8 + t;
    const float* W = Wg + ((size_t)l * HEADS + head) * HID * FOUT;
    g_Wp2[idx] = make_float2(tf32r(W[(size_t)k * FOUT + d]),
                             tf32r(W[(size_t)(k + 4) * FOUT + d]));
}
__global__ void k0_pack_w1(const float* __restrict__ Wm) {
    int idx = blockIdx.x * 256 + threadIdx.x;     // [4][4][4][128][4]
    if (idx >= 4 * 4 * 4 * 128 * 4) return;
    int t    = idx & 3;
    int c    = (idx >> 2) & 127;
    int g    = (idx >> 9) & 3;
    int s    = (idx >> 11) & 3;
    int tile = idx >> 13;
    int col  = tile * 128 + c;
    int k    = s * 32 + g * 8 + t;
    g_Wp1[idx] = make_float2(tf32r(Wm[(size_t)k * HID + col]),
                             tf32r(Wm[(size_t)(k + 4) * HID + col]));
}
__global__ void k0_colsum_wm(const float* __restrict__ Wm) {
    int c = blockIdx.x * 128 + threadIdx.x;   // grid 4 x 128
    float s = 0.f;
#pragma unroll 8
    for (int k = 0; k < FIN; k++) s += tf32r(Wm[(size_t)k * HID + c]);
    g_cs[c] = s;
}

// ===========================================================================
// shared GEMM tile config — packed B: stage = A(18432) + B(16384) = 34816
// NBUF=3 -> 104448 B -> 2 CTAs/SM
// ===========================================================================
#define TM 128
#define TN 128
#define KC 32
#define NBUF 3
#define A_STRIDE 36
#define A_BYTES (TM * A_STRIDE * 4)        // 18432
#define B_BYTES 16384
#define STAGE_BYTES (A_BYTES + B_BYTES)    // 34816
#define K2_SMEM (NBUF * STAGE_BYTES)       // 104448

__device__ __forceinline__ int slot3(int s) { return s - (s / 3) * 3; }

// ===========================================================================
// K1M (tf32 mma): h_x = s_row*(x @ Wm) + t_row*colsum(Wm) + b  (packed B)
// ===========================================================================
__global__ __launch_bounds__(256, 2) void k1_mma(
    const float* __restrict__ x,
    const float* __restrict__ gamma, const float* __restrict__ beta,
    const float* __restrict__ mean,  const float* __restrict__ var,
    const float* __restrict__ bm)
{
    extern __shared__ __align__(16) char smem[];
    const int NS_K = FIN / KC;   // 4
    const int tid  = threadIdx.x;
    const int lane = tid & 31;
    const int wid  = tid >> 5;
    const int wm   = wid & 3;
    const int wn   = wid >> 2;
    const int tile = blockIdx.x;
    const int n0   = tile * TN;
    const int row0 = blockIdx.y * TM;
    const uint32_t sbase = smem_u32(smem);

    auto issue_stage = [&](int s) {
        const int p = slot3(s);
        const float* Ag = x + (size_t)row0 * FIN + s * KC;
        const uint32_t Ad = sbase + p * STAGE_BYTES;
#pragma unroll
        for (int i = 0; i < 4; i++) {
            int idx = tid + i * 256;
            int r = idx >> 3, k4 = idx & 7;
            cp_async16(Ad + r * (A_STRIDE * 4) + k4 * 16,
                       Ag + (size_t)r * FIN + k4 * 4);
        }
        const uint32_t Bd = sbase + p * STAGE_BYTES + A_BYTES;
        const char* Bsrc = (const char*)(g_Wp1 + ((size_t)(tile * 4 + s)) * 2048);
#pragma unroll
        for (int i = 0; i < 4; i++) {
            int idx = tid + i * 256;
            cp_async16(Bd + idx * 16, Bsrc + idx * 16);
        }
    };

    float acc[2][8][4];
#pragma unroll
    for (int mt = 0; mt < 2; mt++)
#pragma unroll
        for (int nt = 0; nt < 8; nt++)
#pragma unroll
            for (int q = 0; q < 4; q++) acc[mt][nt][q] = 0.f;

#pragma unroll
    for (int s = 0; s < NBUF - 1; s++) { issue_stage(s); cp_commit(); }

#pragma unroll 1
    for (int s = 0; s < NS_K; s++) {
        if (s < NS_K - 1) cp_wait<1>();
        else              cp_wait<0>();
        __syncthreads();
        if (s + NBUF - 1 < NS_K) issue_stage(s + NBUF - 1);
        cp_commit();

        const float* As = (const float*)(smem + slot3(s) * STAGE_BYTES);
        const float2* Bp = (const float2*)((const char*)As + A_BYTES);

#pragma unroll
        for (int ks = 0; ks < KC / 8; ks++) {
            const int kb = ks * 8;
            uint32_t a[2][4], b[8][2];
#pragma unroll
            for (int mt = 0; mt < 2; mt++) {
                int r = wm * 32 + mt * 16 + (lane >> 2);
                int k = kb + (lane & 3);
                a[mt][0] = tf32u(As[r * A_STRIDE + k]);
                a[mt][1] = tf32u(As[(r + 8) * A_STRIDE + k]);
                a[mt][2] = tf32u(As[r * A_STRIDE + k + 4]);
                a[mt][3] = tf32u(As[(r + 8) * A_STRIDE + k + 4]);
            }
#pragma unroll
            for (int nt = 0; nt < 8; nt++) {
                int c = wn * 64 + nt * 8 + (lane >> 2);
                float2 v = Bp[(ks * 128 + c) * 4 + (lane & 3)];
                b[nt][0] = __float_as_uint(v.x);
                b[nt][1] = __float_as_uint(v.y);
            }
#pragma unroll
            for (int mt = 0; mt < 2; mt++)
#pragma unroll
                for (int nt = 0; nt < 8; nt++)
                    mma_tf32(acc[mt][nt], a[mt], b[nt]);
        }
    }

    const int rbase = wm * 32 + (lane >> 2);
    float sv[4], tv[4];
#pragma unroll
    for (int q = 0; q < 4; q++) {
        int r = row0 + rbase + q * 8;
        int n = r % NN;
        float sc = gamma[n] * rsqrtf(var[n] + 1e-5f);
        sv[q] = sc;
        tv[q] = beta[n] - mean[n] * sc;
    }
#pragma unroll
    for (int mt = 0; mt < 2; mt++) {
        int r = row0 + rbase + mt * 16;
#pragma unroll
        for (int nt = 0; nt < 8; nt++) {
            int c = n0 + wn * 64 + nt * 8 + 2 * (lane & 3);
            float cs0 = g_cs[c], cs1 = g_cs[c + 1];
            float b0 = bm[c], b1 = bm[c + 1];
            int q0 = mt * 2, q1 = mt * 2 + 1;
            *(float2*)&g_hx[(size_t)r * HID + c] = make_float2(
                tf32r(sv[q0] * acc[mt][nt][0] + tv[q0] * cs0 + b0),
                tf32r(sv[q0] * acc[mt][nt][1] + tv[q0] * cs1 + b1));
            *(float2*)&g_hx[(size_t)(r + 8) * HID + c] = make_float2(
                tf32r(sv[q1] * acc[mt][nt][2] + tv[q1] * cs0 + b0),
                tf32r(sv[q1] * acc[mt][nt][3] + tv[q1] * cs1 + b1));
        }
    }
}

// ===========================================================================
// K2 (tf32 mma, packed B): g_h = g_hx @ W_gat[l]
// ===========================================================================
__global__ __launch_bounds__(256, 2) void k2_mma(int layer)
{
    extern __shared__ __align__(16) char smem[];
    const int NS_K = HID / KC;   // 16
    const int tid  = threadIdx.x;
    const int lane = tid & 31;
    const int wid  = tid >> 5;
    const int wm   = wid & 3;
    const int wn   = wid >> 2;
    const int tile = blockIdx.x;
    const int n0   = tile * TN;
    const int row0 = blockIdx.y * TM;
    const uint32_t sbase = smem_u32(smem);
    const float2* Wp = g_Wp2 + ((size_t)(layer * 4 + tile) * 16) * 2048;

    auto issue_stage = [&](int s) {
        const int p = slot3(s);
        const float* Ag = g_hx + (size_t)row0 * HID + s * KC;
        const uint32_t Ad = sbase + p * STAGE_BYTES;
#pragma unroll
        for (int i = 0; i < 4; i++) {
            int idx = tid + i * 256;
            int r = idx >> 3, k4 = idx & 7;
            cp_async16(Ad + r * (A_STRIDE * 4) + k4 * 16,
                       Ag + (size_t)r * HID + k4 * 4);
        }
        const uint32_t Bd = sbase + p * STAGE_BYTES + A_BYTES;
        const char* Bsrc = (const char*)(Wp + (size_t)s * 2048);
#pragma unroll
        for (int i = 0; i < 4; i++) {
            int idx = tid + i * 256;
            cp_async16(Bd + idx * 16, Bsrc + idx * 16);
        }
    };

    float acc[2][8][4];
#pragma unroll
    for (int mt = 0; mt < 2; mt++)
#pragma unroll
        for (int nt = 0; nt < 8; nt++)
#pragma unroll
            for (int q = 0; q < 4; q++) acc[mt][nt][q] = 0.f;

#pragma unroll
    for (int s = 0; s < NBUF - 1; s++) { issue_stage(s); cp_commit(); }

#pragma unroll 1
    for (int s = 0; s < NS_K; s++) {
        if (s < NS_K - 1) cp_wait<1>();
        else              cp_wait<0>();
        __syncthreads();
        if (s + NBUF - 1 < NS_K) issue_stage(s + NBUF - 1);
        cp_commit();

        const float* As = (const float*)(smem + slot3(s) * STAGE_BYTES);
        const float2* Bp = (const float2*)((const char*)As + A_BYTES);

#pragma unroll
        for (int ks = 0; ks < KC / 8; ks++) {
            const int kb = ks * 8;
            uint32_t a[2][4], b[8][2];
#pragma unroll
            for (int mt = 0; mt < 2; mt++) {
                int r = wm * 32 + mt * 16 + (lane >> 2);
                int k = kb + (lane & 3);
                a[mt][0] = __float_as_uint(As[r * A_STRIDE + k]);
                a[mt][1] = __float_as_uint(As[(r + 8) * A_STRIDE + k]);
                a[mt][2] = __float_as_uint(As[r * A_STRIDE + k + 4]);
                a[mt][3] = __float_as_uint(As[(r + 8) * A_STRIDE + k + 4]);
            }
#pragma unroll
            for (int nt = 0; nt < 8; nt++) {
                int c = wn * 64 + nt * 8 + (lane >> 2);
                float2 v = Bp[(ks * 128 + c) * 4 + (lane & 3)];
                b[nt][0] = __float_as_uint(v.x);
                b[nt][1] = __float_as_uint(v.y);
            }
#pragma unroll
            for (int mt = 0; mt < 2; mt++)
#pragma unroll
                for (int nt = 0; nt < 8; nt++)
                    mma_tf32(acc[mt][nt], a[mt], b[nt]);
        }
    }

#pragma unroll
    for (int mt = 0; mt < 2; mt++) {
        int r = row0 + wm * 32 + mt * 16 + (lane >> 2);
#pragma unroll
        for (int nt = 0; nt < 8; nt++) {
            int c = n0 + wn * 64 + nt * 8 + 2 * (lane & 3);
            *(float2*)&g_h[(size_t)r * HID + c] =
                make_float2(acc[mt][nt][0], acc[mt][nt][1]);
            *(float2*)&g_h[(size_t)(r + 8) * HID + c] =
                make_float2(acc[mt][nt][2], acc[mt][nt][3]);
        }
    }
}

// ===========================================================================
// K4: per-b attention, 8-head loop, smem adj mask.
//  - exp pass FUSED with column sums (each thread owns one column)
//  - last==1 (layer 2): output pooled in-block, + W_out head + log_softmax
//    (k5 and layer-2's g_hx roundtrip eliminated)
// ===========================================================================
#define HS_STR 72
#define ES_STR 68

__global__ __launch_bounds__(256) void k4_attn(
    const int* __restrict__ adj, const float* __restrict__ a_l, int last,
    const float* __restrict__ Wout, const float* __restrict__ bout,
    float* __restrict__ out)
{
    __shared__ float hs[64][HS_STR];
    __shared__ float es[64][ES_STR];
    __shared__ unsigned char mask[64 * 64];
    __shared__ float asv[2 * FOUT];
    __shared__ float f1[64], f2[64];
    __shared__ float ps[4][64];
    __shared__ float rsv[64];
    __shared__ float pooled[HID];

    const int b    = blockIdx.x;
    const int tid  = threadIdx.x;
    const int lane = tid & 31;
    const int wid  = tid >> 5;

    const int* adjb = adj + (size_t)b * NN * NN;
    for (int idx = tid; idx < 64 * 64; idx += 256) {
        int i = idx >> 6, j = idx & 63;
        mask[idx] = (i < NN && j < NN && adjb[i * NN + j] > 0) ? 1 : 0;
    }
    if (last) {
        pooled[tid] = 0.f;
        pooled[tid + 256] = 0.f;
    }

    const float* hrow = &g_h[(size_t)b * NN * HID];
    float* orow = &g_hx[(size_t)b * NN * HID];

#pragma unroll 1
    for (int head = 0; head < HEADS; head++) {
        __syncthreads();

        const float* hbase = hrow + head * FOUT;
        for (int idx = tid; idx < 64 * 16; idx += 256) {
            int j = idx >> 4, d4 = idx & 15;
            float4 v = (j < NN) ? *(const float4*)(hbase + (size_t)j * HID + d4 * 4)
                                : make_float4(0.f, 0.f, 0.f, 0.f);
            *(float4*)&hs[j][d4 * 4] = v;
        }
        if (tid < 2 * FOUT) asv[tid] = a_l[head * 2 * FOUT + tid];
        __syncthreads();

        // f1/f2
        {
            int node = tid >> 2, t = tid & 3;
            float s1 = 0.f, s2 = 0.f;
#pragma unroll
            for (int dd = 0; dd < 16; dd++) {
                int d = t * 16 + dd;
                float v = hs[node][d];
                s1 += v * asv[d];
                s2 += v * asv[FOUT + d];
            }
            s1 += __shfl_xor_sync(0xffffffffu, s1, 1);
            s1 += __shfl_xor_sync(0xffffffffu, s1, 2);
            s2 += __shfl_xor_sync(0xffffffffu, s2, 1);
            s2 += __shfl_xor_sync(0xffffffffu, s2, 2);
            if (t == 0) { f1[node] = s1; f2[node] = s2; }
        }
        __syncthreads();

        // fused: es[i][j] = tf32r(exp(leaky(...))) masked, + column partial sum
        // (thread owns column j = tid&63, rows i = (tid>>6) + 4k)
        {
            int q = tid >> 6, j = tid & 63;
            float f1j = f1[j];
            float ssum = 0.f;
#pragma unroll
            for (int k = 0; k < 16; k++) {
                int idx = tid + k * 256;
                int i = idx >> 6;
                float e = 0.f;
                if (mask[idx]) {
                    float v = f2[i] + f1j;
                    v = v > 0.f ? v : 0.2f * v;
                    e = tf32r(__expf(v));
                }
                es[i][j] = e;
                ssum += e;
            }
            ps[q][j] = ssum;
        }
        __syncthreads();
        if (tid < 64) {
            float s = ps[0][tid] + ps[1][tid] + ps[2][tid] + ps[3][tid];
            rsv[tid] = (s > 0.f) ? 1.f / s : 0.f;
        }
        __syncthreads();

        // fold 1/colsum[j] into hs row j, round to tf32
        for (int idx = tid; idx < 64 * 16; idx += 256) {
            int j = idx >> 4, d4 = idx & 15;
            float rs = rsv[j];
            float4 v = *(float4*)&hs[j][d4 * 4];
            v.x = tf32r(v.x * rs); v.y = tf32r(v.y * rs);
            v.z = tf32r(v.z * rs); v.w = tf32r(v.w * rs);
            *(float4*)&hs[j][d4 * 4] = v;
        }
        __syncthreads();

        // tensor-core aggregation D = es @ hs
        const int wm = wid & 3, wn = wid >> 2;
        float acc[4][4];
#pragma unroll
        for (int nt = 0; nt < 4; nt++)
#pragma unroll
            for (int q = 0; q < 4; q++) acc[nt][q] = 0.f;

        const int r = wm * 16 + (lane >> 2);
#pragma unroll
        for (int kb = 0; kb < 64; kb += 8) {
            const int k = kb + (lane & 3);
            uint32_t a[4];
            a[0] = __float_as_uint(es[r][k]);
            a[1] = __float_as_uint(es[r + 8][k]);
            a[2] = __float_as_uint(es[r][k + 4]);
            a[3] = __float_as_uint(es[r + 8][k + 4]);
#pragma unroll
            for (int nt = 0; nt < 4; nt++) {
                const int c = wn * 32 + nt * 8 + (lane >> 2);
                uint32_t bb[2];
                bb[0] = __float_as_uint(hs[k][c]);
                bb[1] = __float_as_uint(hs[k + 4][c]);
                mma_tf32(acc[nt], a, bb);
            }
        }

        const int i0 = wm * 16 + (lane >> 2);
        const int i1 = i0 + 8;

        if (!last) {
            // ELU + tf32 round + store to g_hx
            float* ob = orow + head * FOUT;
#pragma unroll
            for (int nt = 0; nt < 4; nt++) {
                int c = wn * 32 + nt * 8 + 2 * (lane & 3);
                float v0 = acc[nt][0], v1 = acc[nt][1];
                v0 = v0 > 0.f ? v0 : expm1f(v0);
                v1 = v1 > 0.f ? v1 : expm1f(v1);
                *(float2*)(ob + (size_t)i0 * HID + c) =
                    make_float2(tf32r(v0), tf32r(v1));
                if (i1 < NN) {
                    float v2 = acc[nt][2], v3 = acc[nt][3];
                    v2 = v2 > 0.f ? v2 : expm1f(v2);
                    v3 = v3 > 0.f ? v3 : expm1f(v3);
                    *(float2*)(ob + (size_t)i1 * HID + c) =
                        make_float2(tf32r(v2), tf32r(v3));
                }
            }
        } else {
            // stage ELU output in hs (pad rows produce ELU(0)=0), then
            // column-sum into pooled[head*64 + c]
            __syncthreads();   // all MMA reads of hs done
#pragma unroll
            for (int nt = 0; nt < 4; nt++) {
                int c = wn * 32 + nt * 8 + 2 * (lane & 3);
                float v0 = acc[nt][0], v1 = acc[nt][1];
                float v2 = acc[nt][2], v3 = acc[nt][3];
                v0 = v0 > 0.f ? v0 : expm1f(v0);
                v1 = v1 > 0.f ? v1 : expm1f(v1);
                v2 = v2 > 0.f ? v2 : expm1f(v2);
                v3 = v3 > 0.f ? v3 : expm1f(v3);
                *(float2*)&hs[i0][c] = make_float2(v0, v1);
                *(float2*)&hs[i1][c] = make_float2(v2, v3);   // rows 62,63 = 0
            }
            __syncthreads();
            {
                int q = tid >> 6, c = tid & 63;
                float s = 0.f;
#pragma unroll
                for (int k = 0; k < 16; k++) s += hs[q + k * 4][c];
                ps[q][c] = s;
            }
            __syncthreads();
            if (tid < 64)
                pooled[head * FOUT + tid] +=
                    ps[0][tid] + ps[1][tid] + ps[2][tid] + ps[3][tid];
        }
    }

    if (last) {
        __syncthreads();
        // logits = pooled @ Wout + bout; log_softmax; write out[b]
        float l0 = 0.f, l1 = 0.f, l2 = 0.f;
#pragma unroll
        for (int c = tid; c < HID; c += 256) {
            float p = pooled[c];
            l0 += p * Wout[c * 3 + 0];
            l1 += p * Wout[c * 3 + 1];
            l2 += p * Wout[c * 3 + 2];
        }
#pragma unroll
        for (int off = 16; off > 0; off >>= 1) {
            l0 += __shfl_down_sync(0xffffffffu, l0, off);
            l1 += __shfl_down_sync(0xffffffffu, l1, off);
            l2 += __shfl_down_sync(0xffffffffu, l2, off);
        }
        if (lane == 0) { ps[0][wid] = l0; ps[1][wid] = l1; ps[2][wid] = l2; }
        __syncthreads();
        if (tid == 0) {
            float lg[3];
#pragma unroll
            for (int c = 0; c < 3; c++) {
                float t = 0.f;
#pragma unroll
                for (int w = 0; w < 8; w++) t += ps[c][w];
                lg[c] = t + bout[c];
            }
            float m = fmaxf(lg[0], fmaxf(lg[1], lg[2]));
            float sum = expf(lg[0] - m) + expf(lg[1] - m) + expf(lg[2] - m);
            float lse = logf(sum) + m;
            out[b * 3 + 0] = lg[0] - lse;
            out[b * 3 + 1] = lg[1] - lse;
            out[b * 3 + 2] = lg[2] - lse;
        }
    }
}

// ===========================================================================
extern "C" void kernel_launch(void* const* d_in, const int* in_sizes, int n_in,
                              void* d_out, int out_size)
{
    const float* x     = (const float*)d_in[0];
    const int*   adj   = (const int*)  d_in[1];
    const float* gamma = (const float*)d_in[2];
    const float* beta  = (const float*)d_in[3];
    const float* mean  = (const float*)d_in[4];
    const float* var   = (const float*)d_in[5];
    const float* Wm    = (const float*)d_in[6];
    const float* bm    = (const float*)d_in[7];
    const float* Wg    = (const float*)d_in[8];
    const float* ag    = (const float*)d_in[9];
    const float* Wo    = (const float*)d_in[10];
    const float* bo    = (const float*)d_in[11];
    float* out = (float*)d_out;

    cudaFuncSetAttribute(k2_mma, cudaFuncAttributeMaxDynamicSharedMemorySize, K2_SMEM);
    cudaFuncSetAttribute(k1_mma, cudaFuncAttributeMaxDynamicSharedMemorySize, K2_SMEM);

    k0_pack_w2<<<(3 * 4 * 16 * 4 * 128 * 4) / 256, 256>>>(Wg);
    k0_pack_w1<<<(4 * 4 * 4 * 128 * 4) / 256, 256>>>(Wm);
    k0_colsum_wm<<<4, 128>>>(Wm);

    k1_mma<<<dim3(HID / TN, NROWS / TM), 256, K2_SMEM>>>(x, gamma, beta, mean, var, bm);

    for (int l = 0; l < 3; l++) {
        k2_mma<<<dim3(HID / TN, NROWS / TM), 256, K2_SMEM>>>(l);
        k4_attn<<<BB, 256>>>(adj, ag + (size_t)l * HEADS * 2 * FOUT,
                             l == 2 ? 1 : 0, Wo, bo, out);
    }
}

// round 15
// speedup vs baseline: 1.1237x; 1.1237x over previous
#include <cuda_runtime.h>
#include <math.h>
#include <cstdint>

#define BB    2048
#define NN    62
#define FIN   128
#define HID   512
#define HEADS 8
#define FOUT  64
#define NROWS (BB * NN)   // 126976

__device__ float g_hx[(size_t)NROWS * HID];
__device__ float g_h [(size_t)NROWS * HID];
__device__ float g_cs[HID];
// packed weights: smem-image layout [tile][stage][g][c][t] of float2 pairs
__device__ float2 g_Wp2[3 * 4 * 16 * 4 * 128 * 4];   // GAT W, 3 layers
__device__ float2 g_Wp1[4 * 4 * 4 * 128 * 4];        // W_mlp

// ===========================================================================
// helpers
// ===========================================================================
__device__ __forceinline__ uint32_t smem_u32(const void* p) {
    uint32_t a;
    asm("{ .reg .u64 t; cvta.to.shared.u64 t, %1; cvt.u32.u64 %0, t; }"
        : "=r"(a) : "l"(p));
    return a;
}
__device__ __forceinline__ float tf32r(float x) {
    uint32_t u;
    asm("cvt.rna.tf32.f32 %0, %1;" : "=r"(u) : "f"(x));
    return __uint_as_float(u);
}
__device__ __forceinline__ uint32_t tf32u(float x) {
    uint32_t u;
    asm("cvt.rna.tf32.f32 %0, %1;" : "=r"(u) : "f"(x));
    return u;
}
__device__ __forceinline__ void cp_async16(uint32_t dst, const void* src) {
    asm volatile("cp.async.cg.shared.global [%0], [%1], 16;"
                 :: "r"(dst), "l"(src) : "memory");
}
__device__ __forceinline__ void cp_commit() {
    asm volatile("cp.async.commit_group;" ::: "memory");
}
template <int N>
__device__ __forceinline__ void cp_wait() {
    asm volatile("cp.async.wait_group %0;" :: "n"(N) : "memory");
}
__device__ __forceinline__ void mma_tf32(float* c, const uint32_t* a, const uint32_t* b) {
    asm volatile(
        "mma.sync.aligned.m16n8k8.row.col.f32.tf32.tf32.f32 "
        "{%0,%1,%2,%3}, {%4,%5,%6,%7}, {%8,%9}, {%0,%1,%2,%3};"
        : "+f"(c[0]), "+f"(c[1]), "+f"(c[2]), "+f"(c[3])
        : "r"(a[0]), "r"(a[1]), "r"(a[2]), "r"(a[3]), "r"(b[0]), "r"(b[1]));
}

// ===========================================================================
// K0: weight packing (one-time)
// ===========================================================================
__global__ void k0_pack_w2(const float* __restrict__ Wg) {
    int idx = blockIdx.x * 256 + threadIdx.x;     // [3][4][16][4][128][4]
    if (idx >= 3 * 4 * 16 * 4 * 128 * 4) return;
    int t    = idx & 3;
    int c    = (idx >> 2) & 127;
    int g    = (idx >> 9) & 3;
    int s    = (idx >> 11) & 15;
    int tile = (idx >> 15) & 3;
    int l    = idx >> 17;
    int col  = tile * 128 + c;
    int head = col >> 6, d = col & 63;
    int k    = s * 32 + g * 8 + t;
    const float* W = Wg + ((size_t)l * HEADS + head) * HID * FOUT;
    g_Wp2[idx] = make_float2(tf32r(W[(size_t)k * FOUT + d]),
                             tf32r(W[(size_t)(k + 4) * FOUT + d]));
}
__global__ void k0_pack_w1(const float* __restrict__ Wm) {
    int idx = blockIdx.x * 256 + threadIdx.x;     // [4][4][4][128][4]
    if (idx >= 4 * 4 * 4 * 128 * 4) return;
    int t    = idx & 3;
    int c    = (idx >> 2) & 127;
    int g    = (idx >> 9) & 3;
    int s    = (idx >> 11) & 3;
    int tile = idx >> 13;
    int col  = tile * 128 + c;
    int k    = s * 32 + g * 8 + t;
    g_Wp1[idx] = make_float2(tf32r(Wm[(size_t)k * HID + col]),
                             tf32r(Wm[(size_t)(k + 4) * HID + col]));
}
__global__ void k0_colsum_wm(const float* __restrict__ Wm) {
    int c = blockIdx.x * 128 + threadIdx.x;   // grid 4 x 128
    float s = 0.f;
#pragma unroll 8
    for (int k = 0; k < FIN; k++) s += tf32r(Wm[(size_t)k * HID + c]);
    g_cs[c] = s;
}

// ===========================================================================
// shared GEMM tile config — packed B
// ===========================================================================
#define TM 128
#define TN 128
#define KC 32
#define NBUF 3
#define A_STRIDE 36
#define A_BYTES (TM * A_STRIDE * 4)        // 18432
#define B_BYTES 16384
#define STAGE_BYTES (A_BYTES + B_BYTES)    // 34816
#define K2_SMEM (NBUF * STAGE_BYTES)       // 104448

__device__ __forceinline__ int slot3(int s) { return s - (s / 3) * 3; }

// ===========================================================================
// K1M (tf32 mma): h_x = s_row*(x @ Wm) + t_row*colsum(Wm) + b  (packed B)
// ===========================================================================
__global__ __launch_bounds__(256, 2) void k1_mma(
    const float* __restrict__ x,
    const float* __restrict__ gamma, const float* __restrict__ beta,
    const float* __restrict__ mean,  const float* __restrict__ var,
    const float* __restrict__ bm)
{
    extern __shared__ __align__(16) char smem[];
    const int NS_K = FIN / KC;   // 4
    const int tid  = threadIdx.x;
    const int lane = tid & 31;
    const int wid  = tid >> 5;
    const int wm   = wid & 3;
    const int wn   = wid >> 2;
    const int tile = blockIdx.x;
    const int n0   = tile * TN;
    const int row0 = blockIdx.y * TM;
    const uint32_t sbase = smem_u32(smem);

    auto issue_stage = [&](int s) {
        const int p = slot3(s);
        const float* Ag = x + (size_t)row0 * FIN + s * KC;
        const uint32_t Ad = sbase + p * STAGE_BYTES;
#pragma unroll
        for (int i = 0; i < 4; i++) {
            int idx = tid + i * 256;
            int r = idx >> 3, k4 = idx & 7;
            cp_async16(Ad + r * (A_STRIDE * 4) + k4 * 16,
                       Ag + (size_t)r * FIN + k4 * 4);
        }
        const uint32_t Bd = sbase + p * STAGE_BYTES + A_BYTES;
        const char* Bsrc = (const char*)(g_Wp1 + ((size_t)(tile * 4 + s)) * 2048);
#pragma unroll
        for (int i = 0; i < 4; i++) {
            int idx = tid + i * 256;
            cp_async16(Bd + idx * 16, Bsrc + idx * 16);
        }
    };

    float acc[2][8][4];
#pragma unroll
    for (int mt = 0; mt < 2; mt++)
#pragma unroll
        for (int nt = 0; nt < 8; nt++)
#pragma unroll
            for (int q = 0; q < 4; q++) acc[mt][nt][q] = 0.f;

#pragma unroll
    for (int s = 0; s < NBUF - 1; s++) { issue_stage(s); cp_commit(); }

#pragma unroll 1
    for (int s = 0; s < NS_K; s++) {
        if (s < NS_K - 1) cp_wait<1>();
        else              cp_wait<0>();
        __syncthreads();
        if (s + NBUF - 1 < NS_K) issue_stage(s + NBUF - 1);
        cp_commit();

        const float* As = (const float*)(smem + slot3(s) * STAGE_BYTES);
        const float2* Bp = (const float2*)((const char*)As + A_BYTES);

#pragma unroll
        for (int ks = 0; ks < KC / 8; ks++) {
            const int kb = ks * 8;
            uint32_t a[2][4], b[8][2];
#pragma unroll
            for (int mt = 0; mt < 2; mt++) {
                int r = wm * 32 + mt * 16 + (lane >> 2);
                int k = kb + (lane & 3);
                a[mt][0] = tf32u(As[r * A_STRIDE + k]);
                a[mt][1] = tf32u(As[(r + 8) * A_STRIDE + k]);
                a[mt][2] = tf32u(As[r * A_STRIDE + k + 4]);
                a[mt][3] = tf32u(As[(r + 8) * A_STRIDE + k + 4]);
            }
#pragma unroll
            for (int nt = 0; nt < 8; nt++) {
                int c = wn * 64 + nt * 8 + (lane >> 2);
                float2 v = Bp[(ks * 128 + c) * 4 + (lane & 3)];
                b[nt][0] = __float_as_uint(v.x);
                b[nt][1] = __float_as_uint(v.y);
            }
#pragma unroll
            for (int mt = 0; mt < 2; mt++)
#pragma unroll
                for (int nt = 0; nt < 8; nt++)
                    mma_tf32(acc[mt][nt], a[mt], b[nt]);
        }
    }

    const int rbase = wm * 32 + (lane >> 2);
    float sv[4], tv[4];
#pragma unroll
    for (int q = 0; q < 4; q++) {
        int r = row0 + rbase + q * 8;
        int n = r % NN;
        float sc = gamma[n] * rsqrtf(var[n] + 1e-5f);
        sv[q] = sc;
        tv[q] = beta[n] - mean[n] * sc;
    }
#pragma unroll
    for (int mt = 0; mt < 2; mt++) {
        int r = row0 + rbase + mt * 16;
#pragma unroll
        for (int nt = 0; nt < 8; nt++) {
            int c = n0 + wn * 64 + nt * 8 + 2 * (lane & 3);
            float cs0 = g_cs[c], cs1 = g_cs[c + 1];
            float b0 = bm[c], b1 = bm[c + 1];
            int q0 = mt * 2, q1 = mt * 2 + 1;
            *(float2*)&g_hx[(size_t)r * HID + c] = make_float2(
                tf32r(sv[q0] * acc[mt][nt][0] + tv[q0] * cs0 + b0),
                tf32r(sv[q0] * acc[mt][nt][1] + tv[q0] * cs1 + b1));
            *(float2*)&g_hx[(size_t)(r + 8) * HID + c] = make_float2(
                tf32r(sv[q1] * acc[mt][nt][2] + tv[q1] * cs0 + b0),
                tf32r(sv[q1] * acc[mt][nt][3] + tv[q1] * cs1 + b1));
        }
    }
}

// ===========================================================================
// K2 (tf32 mma, packed B): g_h = g_hx @ W_gat[l]
// ===========================================================================
__global__ __launch_bounds__(256, 2) void k2_mma(int layer)
{
    extern __shared__ __align__(16) char smem[];
    const int NS_K = HID / KC;   // 16
    const int tid  = threadIdx.x;
    const int lane = tid & 31;
    const int wid  = tid >> 5;
    const int wm   = wid & 3;
    const int wn   = wid >> 2;
    const int tile = blockIdx.x;
    const int n0   = tile * TN;
    const int row0 = blockIdx.y * TM;
    const uint32_t sbase = smem_u32(smem);
    const float2* Wp = g_Wp2 + ((size_t)(layer * 4 + tile) * 16) * 2048;

    auto issue_stage = [&](int s) {
        const int p = slot3(s);
        const float* Ag = g_hx + (size_t)row0 * HID + s * KC;
        const uint32_t Ad = sbase + p * STAGE_BYTES;
#pragma unroll
        for (int i = 0; i < 4; i++) {
            int idx = tid + i * 256;
            int r = idx >> 3, k4 = idx & 7;
            cp_async16(Ad + r * (A_STRIDE * 4) + k4 * 16,
                       Ag + (size_t)r * HID + k4 * 4);
        }
        const uint32_t Bd = sbase + p * STAGE_BYTES + A_BYTES;
        const char* Bsrc = (const char*)(Wp + (size_t)s * 2048);
#pragma unroll
        for (int i = 0; i < 4; i++) {
            int idx = tid + i * 256;
            cp_async16(Bd + idx * 16, Bsrc + idx * 16);
        }
    };

    float acc[2][8][4];
#pragma unroll
    for (int mt = 0; mt < 2; mt++)
#pragma unroll
        for (int nt = 0; nt < 8; nt++)
#pragma unroll
            for (int q = 0; q < 4; q++) acc[mt][nt][q] = 0.f;

#pragma unroll
    for (int s = 0; s < NBUF - 1; s++) { issue_stage(s); cp_commit(); }

#pragma unroll 1
    for (int s = 0; s < NS_K; s++) {
        if (s < NS_K - 1) cp_wait<1>();
        else              cp_wait<0>();
        __syncthreads();
        if (s + NBUF - 1 < NS_K) issue_stage(s + NBUF - 1);
        cp_commit();

        const float* As = (const float*)(smem + slot3(s) * STAGE_BYTES);
        const float2* Bp = (const float2*)((const char*)As + A_BYTES);

#pragma unroll
        for (int ks = 0; ks < KC / 8; ks++) {
            const int kb = ks * 8;
            uint32_t a[2][4], b[8][2];
#pragma unroll
            for (int mt = 0; mt < 2; mt++) {
                int r = wm * 32 + mt * 16 + (lane >> 2);
                int k = kb + (lane & 3);
                a[mt][0] = __float_as_uint(As[r * A_STRIDE + k]);
                a[mt][1] = __float_as_uint(As[(r + 8) * A_STRIDE + k]);
                a[mt][2] = __float_as_uint(As[r * A_STRIDE + k + 4]);
                a[mt][3] = __float_as_uint(As[(r + 8) * A_STRIDE + k + 4]);
            }
#pragma unroll
            for (int nt = 0; nt < 8; nt++) {
                int c = wn * 64 + nt * 8 + (lane >> 2);
                float2 v = Bp[(ks * 128 + c) * 4 + (lane & 3)];
                b[nt][0] = __float_as_uint(v.x);
                b[nt][1] = __float_as_uint(v.y);
            }
#pragma unroll
            for (int mt = 0; mt < 2; mt++)
#pragma unroll
                for (int nt = 0; nt < 8; nt++)
                    mma_tf32(acc[mt][nt], a[mt], b[nt]);
        }
    }

#pragma unroll
    for (int mt = 0; mt < 2; mt++) {
        int r = row0 + wm * 32 + mt * 16 + (lane >> 2);
#pragma unroll
        for (int nt = 0; nt < 8; nt++) {
            int c = n0 + wn * 64 + nt * 8 + 2 * (lane & 3);
            *(float2*)&g_h[(size_t)r * HID + c] =
                make_float2(acc[mt][nt][0], acc[mt][nt][1]);
            *(float2*)&g_h[(size_t)(r + 8) * HID + c] =
                make_float2(acc[mt][nt][2], acc[mt][nt][3]);
        }
    }
}

// ===========================================================================
// K4 (layers 0,1): per-b attention, 8-head loop, smem adj mask —
// round-13 version, byte-for-byte.
// ===========================================================================
#define HS_STR 72
#define ES_STR 68

__global__ __launch_bounds__(256) void k4_attn(
    const int* __restrict__ adj, const float* __restrict__ a_l)
{
    __shared__ float hs[64][HS_STR];
    __shared__ float es[64][ES_STR];
    __shared__ unsigned char mask[64 * 64];
    __shared__ float asv[2 * FOUT];
    __shared__ float f1[64], f2[64];
    __shared__ float ps[4][64];
    __shared__ float rsv[64];

    const int b    = blockIdx.x;
    const int tid  = threadIdx.x;
    const int lane = tid & 31;
    const int wid  = tid >> 5;

    const int* adjb = adj + (size_t)b * NN * NN;
    for (int idx = tid; idx < 64 * 64; idx += 256) {
        int i = idx >> 6, j = idx & 63;
        mask[idx] = (i < NN && j < NN && adjb[i * NN + j] > 0) ? 1 : 0;
    }

    const float* hrow = &g_h[(size_t)b * NN * HID];
    float* orow = &g_hx[(size_t)b * NN * HID];

#pragma unroll 1
    for (int head = 0; head < HEADS; head++) {
        __syncthreads();

        const float* hbase = hrow + head * FOUT;
        for (int idx = tid; idx < 64 * 16; idx += 256) {
            int j = idx >> 4, d4 = idx & 15;
            float4 v = (j < NN) ? *(const float4*)(hbase + (size_t)j * HID + d4 * 4)
                                : make_float4(0.f, 0.f, 0.f, 0.f);
            *(float4*)&hs[j][d4 * 4] = v;
        }
        if (tid < 2 * FOUT) asv[tid] = a_l[head * 2 * FOUT + tid];
        __syncthreads();

        {
            int node = tid >> 2, t = tid & 3;
            float s1 = 0.f, s2 = 0.f;
#pragma unroll
            for (int dd = 0; dd < 16; dd++) {
                int d = t * 16 + dd;
                float v = hs[node][d];
                s1 += v * asv[d];
                s2 += v * asv[FOUT + d];
            }
            s1 += __shfl_xor_sync(0xffffffffu, s1, 1);
            s1 += __shfl_xor_sync(0xffffffffu, s1, 2);
            s2 += __shfl_xor_sync(0xffffffffu, s2, 1);
            s2 += __shfl_xor_sync(0xffffffffu, s2, 2);
            if (t == 0) { f1[node] = s1; f2[node] = s2; }
        }
        __syncthreads();

        for (int idx = tid; idx < 64 * 64; idx += 256) {
            int i = idx >> 6, j = idx & 63;
            float e = 0.f;
            if (mask[idx]) {
                float v = f2[i] + f1[j];
                v = v > 0.f ? v : 0.2f * v;
                e = tf32r(__expf(v));
            }
            es[i][j] = e;
        }
        __syncthreads();

        {
            int j = tid & 63, q = tid >> 6;
            float s = 0.f;
#pragma unroll
            for (int ii = 0; ii < 16; ii++) s += es[q + ii * 4][j];
            ps[q][j] = s;
        }
        __syncthreads();
        if (tid < 64) {
            float s = ps[0][tid] + ps[1][tid] + ps[2][tid] + ps[3][tid];
            rsv[tid] = (s > 0.f) ? 1.f / s : 0.f;
        }
        __syncthreads();

        for (int idx = tid; idx < 64 * 16; idx += 256) {
            int j = idx >> 4, d4 = idx & 15;
            float rs = rsv[j];
            float4 v = *(float4*)&hs[j][d4 * 4];
            v.x = tf32r(v.x * rs); v.y = tf32r(v.y * rs);
            v.z = tf32r(v.z * rs); v.w = tf32r(v.w * rs);
            *(float4*)&hs[j][d4 * 4] = v;
        }
        __syncthreads();

        {
            const int wm = wid & 3, wn = wid >> 2;
            float acc[4][4];
#pragma unroll
            for (int nt = 0; nt < 4; nt++)
#pragma unroll
                for (int q = 0; q < 4; q++) acc[nt][q] = 0.f;

            const int r = wm * 16 + (lane >> 2);
#pragma unroll
            for (int kb = 0; kb < 64; kb += 8) {
                const int k = kb + (lane & 3);
                uint32_t a[4];
                a[0] = __float_as_uint(es[r][k]);
                a[1] = __float_as_uint(es[r + 8][k]);
                a[2] = __float_as_uint(es[r][k + 4]);
                a[3] = __float_as_uint(es[r + 8][k + 4]);
#pragma unroll
                for (int nt = 0; nt < 4; nt++) {
                    const int c = wn * 32 + nt * 8 + (lane >> 2);
                    uint32_t bb[2];
                    bb[0] = __float_as_uint(hs[k][c]);
                    bb[1] = __float_as_uint(hs[k + 4][c]);
                    mma_tf32(acc[nt], a, bb);
                }
            }

            const int i0 = wm * 16 + (lane >> 2);
            const int i1 = i0 + 8;
            float* ob = orow + head * FOUT;
#pragma unroll
            for (int nt = 0; nt < 4; nt++) {
                int c = wn * 32 + nt * 8 + 2 * (lane & 3);
                float v0 = acc[nt][0], v1 = acc[nt][1];
                v0 = v0 > 0.f ? v0 : expm1f(v0);
                v1 = v1 > 0.f ? v1 : expm1f(v1);
                *(float2*)(ob + (size_t)i0 * HID + c) =
                    make_float2(tf32r(v0), tf32r(v1));
                if (i1 < NN) {
                    float v2 = acc[nt][2], v3 = acc[nt][3];
                    v2 = v2 > 0.f ? v2 : expm1f(v2);
                    v3 = v3 > 0.f ? v3 : expm1f(v3);
                    *(float2*)(ob + (size_t)i1 * HID + c) =
                        make_float2(tf32r(v2), tf32r(v3));
                }
            }
        }
    }
}

// ===========================================================================
// K4_LAST (layer 2 only): same attention body, but ELU output is pooled
// in-block and fed through W_out + log_softmax (k5 + g_hx roundtrip gone).
// ===========================================================================
__global__ __launch_bounds__(256) void k4_last(
    const int* __restrict__ adj, const float* __restrict__ a_l,
    const float* __restrict__ Wout, const float* __restrict__ bout,
    float* __restrict__ out)
{
    __shared__ float hs[64][HS_STR];
    __shared__ float es[64][ES_STR];
    __shared__ unsigned char mask[64 * 64];
    __shared__ float asv[2 * FOUT];
    __shared__ float f1[64], f2[64];
    __shared__ float ps[4][64];
    __shared__ float rsv[64];
    __shared__ float pooled[HID];

    const int b    = blockIdx.x;
    const int tid  = threadIdx.x;
    const int lane = tid & 31;
    const int wid  = tid >> 5;

    const int* adjb = adj + (size_t)b * NN * NN;
    for (int idx = tid; idx < 64 * 64; idx += 256) {
        int i = idx >> 6, j = idx & 63;
        mask[idx] = (i < NN && j < NN && adjb[i * NN + j] > 0) ? 1 : 0;
    }
    pooled[tid] = 0.f;
    pooled[tid + 256] = 0.f;

    const float* hrow = &g_h[(size_t)b * NN * HID];

#pragma unroll 1
    for (int head = 0; head < HEADS; head++) {
        __syncthreads();

        const float* hbase = hrow + head * FOUT;
        for (int idx = tid; idx < 64 * 16; idx += 256) {
            int j = idx >> 4, d4 = idx & 15;
            float4 v = (j < NN) ? *(const float4*)(hbase + (size_t)j * HID + d4 * 4)
                                : make_float4(0.f, 0.f, 0.f, 0.f);
            *(float4*)&hs[j][d4 * 4] = v;
        }
        if (tid < 2 * FOUT) asv[tid] = a_l[head * 2 * FOUT + tid];
        __syncthreads();

        {
            int node = tid >> 2, t = tid & 3;
            float s1 = 0.f, s2 = 0.f;
#pragma unroll
            for (int dd = 0; dd < 16; dd++) {
                int d = t * 16 + dd;
                float v = hs[node][d];
                s1 += v * asv[d];
                s2 += v * asv[FOUT + d];
            }
            s1 += __shfl_xor_sync(0xffffffffu, s1, 1);
            s1 += __shfl_xor_sync(0xffffffffu, s1, 2);
            s2 += __shfl_xor_sync(0xffffffffu, s2, 1);
            s2 += __shfl_xor_sync(0xffffffffu, s2, 2);
            if (t == 0) { f1[node] = s1; f2[node] = s2; }
        }
        __syncthreads();

        for (int idx = tid; idx < 64 * 64; idx += 256) {
            int i = idx >> 6, j = idx & 63;
            float e = 0.f;
            if (mask[idx]) {
                float v = f2[i] + f1[j];
                v = v > 0.f ? v : 0.2f * v;
                e = tf32r(__expf(v));
            }
            es[i][j] = e;
        }
        __syncthreads();

        {
            int j = tid & 63, q = tid >> 6;
            float s = 0.f;
#pragma unroll
            for (int ii = 0; ii < 16; ii++) s += es[q + ii * 4][j];
            ps[q][j] = s;
        }
        __syncthreads();
        if (tid < 64) {
            float s = ps[0][tid] + ps[1][tid] + ps[2][tid] + ps[3][tid];
            rsv[tid] = (s > 0.f) ? 1.f / s : 0.f;
        }
        __syncthreads();

        for (int idx = tid; idx < 64 * 16; idx += 256) {
            int j = idx >> 4, d4 = idx & 15;
            float rs = rsv[j];
            float4 v = *(float4*)&hs[j][d4 * 4];
            v.x = tf32r(v.x * rs); v.y = tf32r(v.y * rs);
            v.z = tf32r(v.z * rs); v.w = tf32r(v.w * rs);
            *(float4*)&hs[j][d4 * 4] = v;
        }
        __syncthreads();

        {
            const int wm = wid & 3, wn = wid >> 2;
            float acc[4][4];
#pragma unroll
            for (int nt = 0; nt < 4; nt++)
#pragma unroll
                for (int q = 0; q < 4; q++) acc[nt][q] = 0.f;

            const int r = wm * 16 + (lane >> 2);
#pragma unroll
            for (int kb = 0; kb < 64; kb += 8) {
                const int k = kb + (lane & 3);
                uint32_t a[4];
                a[0] = __float_as_uint(es[r][k]);
                a[1] = __float_as_uint(es[r + 8][k]);
                a[2] = __float_as_uint(es[r][k + 4]);
                a[3] = __float_as_uint(es[r + 8][k + 4]);
#pragma unroll
                for (int nt = 0; nt < 4; nt++) {
                    const int c = wn * 32 + nt * 8 + (lane >> 2);
                    uint32_t bb[2];
                    bb[0] = __float_as_uint(hs[k][c]);
                    bb[1] = __float_as_uint(hs[k + 4][c]);
                    mma_tf32(acc[nt], a, bb);
                }
            }

            // stage ELU output back into hs (pad rows write ELU(0)=0), pool
            const int i0 = wm * 16 + (lane >> 2);
            const int i1 = i0 + 8;
            __syncthreads();   // all MMA hs reads done
#pragma unroll
            for (int nt = 0; nt < 4; nt++) {
                int c = wn * 32 + nt * 8 + 2 * (lane & 3);
                float v0 = acc[nt][0], v1 = acc[nt][1];
                float v2 = acc[nt][2], v3 = acc[nt][3];
                v0 = v0 > 0.f ? v0 : expm1f(v0);
                v1 = v1 > 0.f ? v1 : expm1f(v1);
                v2 = v2 > 0.f ? v2 : expm1f(v2);
                v3 = v3 > 0.f ? v3 : expm1f(v3);
                *(float2*)&hs[i0][c] = make_float2(v0, v1);
                *(float2*)&hs[i1][c] = make_float2(v2, v3);
            }
            __syncthreads();
            {
                int q = tid >> 6, c = tid & 63;
                float s = 0.f;
#pragma unroll
                for (int k = 0; k < 16; k++) s += hs[q + k * 4][c];
                ps[q][c] = s;
            }
            __syncthreads();
            if (tid < 64)
                pooled[head * FOUT + tid] +=
                    ps[0][tid] + ps[1][tid] + ps[2][tid] + ps[3][tid];
        }
    }

    __syncthreads();
    float l0 = 0.f, l1 = 0.f, l2 = 0.f;
#pragma unroll
    for (int c = tid; c < HID; c += 256) {
        float p = pooled[c];
        l0 += p * Wout[c * 3 + 0];
        l1 += p * Wout[c * 3 + 1];
        l2 += p * Wout[c * 3 + 2];
    }
#pragma unroll
    for (int off = 16; off > 0; off >>= 1) {
        l0 += __shfl_down_sync(0xffffffffu, l0, off);
        l1 += __shfl_down_sync(0xffffffffu, l1, off);
        l2 += __shfl_down_sync(0xffffffffu, l2, off);
    }
    if (lane == 0) { ps[0][wid] = l0; ps[1][wid] = l1; ps[2][wid] = l2; }
    __syncthreads();
    if (tid == 0) {
        float lg[3];
#pragma unroll
        for (int c = 0; c < 3; c++) {
            float t = 0.f;
#pragma unroll
            for (int w = 0; w < 8; w++) t += ps[c][w];
            lg[c] = t + bout[c];
        }
        float m = fmaxf(lg[0], fmaxf(lg[1], lg[2]));
        float sum = expf(lg[0] - m) + expf(lg[1] - m) + expf(lg[2] - m);
        float lse = logf(sum) + m;
        out[b * 3 + 0] = lg[0] - lse;
        out[b * 3 + 1] = lg[1] - lse;
        out[b * 3 + 2] = lg[2] - lse;
    }
}

// ===========================================================================
extern "C" void kernel_launch(void* const* d_in, const int* in_sizes, int n_in,
                              void* d_out, int out_size)
{
    const float* x     = (const float*)d_in[0];
    const int*   adj   = (const int*)  d_in[1];
    const float* gamma = (const float*)d_in[2];
    const float* beta  = (const float*)d_in[3];
    const float* mean  = (const float*)d_in[4];
    const float* var   = (const float*)d_in[5];
    const float* Wm    = (const float*)d_in[6];
    const float* bm    = (const float*)d_in[7];
    const float* Wg    = (const float*)d_in[8];
    const float* ag    = (const float*)d_in[9];
    const float* Wo    = (const float*)d_in[10];
    const float* bo    = (const float*)d_in[11];
    float* out = (float*)d_out;

    cudaFuncSetAttribute(k2_mma, cudaFuncAttributeMaxDynamicSharedMemorySize, K2_SMEM);
    cudaFuncSetAttribute(k1_mma, cudaFuncAttributeMaxDynamicSharedMemorySize, K2_SMEM);

    k0_pack_w2<<<(3 * 4 * 16 * 4 * 128 * 4) / 256, 256>>>(Wg);
    k0_pack_w1<<<(4 * 4 * 4 * 128 * 4) / 256, 256>>>(Wm);
    k0_colsum_wm<<<4, 128>>>(Wm);

    k1_mma<<<dim3(HID / TN, NROWS / TM), 256, K2_SMEM>>>(x, gamma, beta, mean, var, bm);

    for (int l = 0; l < 2; l++) {
        k2_mma<<<dim3(HID / TN, NROWS / TM), 256, K2_SMEM>>>(l);
        k4_attn<<<BB, 256>>>(adj, ag + (size_t)l * HEADS * 2 * FOUT);
    }
    k2_mma<<<dim3(HID / TN, NROWS / TM), 256, K2_SMEM>>>(2);
    k4_last<<<BB, 256>>>(adj, ag + (size_t)2 * HEADS * 2 * FOUT, Wo, bo, out);
}

// round 17
// speedup vs baseline: 1.1575x; 1.0301x over previous
#include <cuda_runtime.h>
#include <math.h>
#include <cstdint>

#define BB    2048
#define NN    62
#define FIN   128
#define HID   512
#define HEADS 8
#define FOUT  64
#define NROWS (BB * NN)   // 126976

__device__ float g_hx[(size_t)NROWS * HID];
__device__ float g_h [(size_t)NROWS * HID];
__device__ float g_cs[HID];
// packed weights: smem-image layout [tile][stage][g][c][t] of float2 pairs
__device__ float2 g_Wp2[3 * 4 * 16 * 4 * 128 * 4];   // 393216 float2
__device__ float2 g_Wp1[4 * 4 * 4 * 128 * 4];        // 32768 float2

// ===========================================================================
// helpers
// ===========================================================================
__device__ __forceinline__ uint32_t smem_u32(const void* p) {
    uint32_t a;
    asm("{ .reg .u64 t; cvta.to.shared.u64 t, %1; cvt.u32.u64 %0, t; }"
        : "=r"(a) : "l"(p));
    return a;
}
__device__ __forceinline__ float tf32r(float x) {
    uint32_t u;
    asm("cvt.rna.tf32.f32 %0, %1;" : "=r"(u) : "f"(x));
    return __uint_as_float(u);
}
__device__ __forceinline__ uint32_t tf32u(float x) {
    uint32_t u;
    asm("cvt.rna.tf32.f32 %0, %1;" : "=r"(u) : "f"(x));
    return u;
}
__device__ __forceinline__ void cp_async16(uint32_t dst, const void* src) {
    asm volatile("cp.async.cg.shared.global [%0], [%1], 16;"
                 :: "r"(dst), "l"(src) : "memory");
}
__device__ __forceinline__ void cp_commit() {
    asm volatile("cp.async.commit_group;" ::: "memory");
}
template <int N>
__device__ __forceinline__ void cp_wait() {
    asm volatile("cp.async.wait_group %0;" :: "n"(N) : "memory");
}
__device__ __forceinline__ void mma_tf32(float* c, const uint32_t* a, const uint32_t* b) {
    asm volatile(
        "mma.sync.aligned.m16n8k8.row.col.f32.tf32.tf32.f32 "
        "{%0,%1,%2,%3}, {%4,%5,%6,%7}, {%8,%9}, {%0,%1,%2,%3};"
        : "+f"(c[0]), "+f"(c[1]), "+f"(c[2]), "+f"(c[3])
        : "r"(a[0]), "r"(a[1]), "r"(a[2]), "r"(a[3]), "r"(b[0]), "r"(b[1]));
}

// ===========================================================================
// K0 (merged, FIXED block ranges): pack W_gat [0,1536), pack W_mlp
// [1536,1664), colsum W_mlp block 1664. Grid 1665.
// ===========================================================================
#define K0_W2_BLKS 1536    // 393216 / 256
#define K0_W1_BLKS 128     // 32768 / 256

__global__ void k0_all(const float* __restrict__ Wg, const float* __restrict__ Wm) {
    int bidx = blockIdx.x;
    if (bidx < K0_W2_BLKS) {
        int idx = bidx * 256 + threadIdx.x;     // [3][4][16][4][128][4]
        int t    = idx & 3;
        int c    = (idx >> 2) & 127;
        int g    = (idx >> 9) & 3;
        int s    = (idx >> 11) & 15;
        int tile = (idx >> 15) & 3;
        int l    = idx >> 17;                   // idx < 393216 = 3<<17
        int col  = tile * 128 + c;
        int head = col >> 6, d = col & 63;
        int k    = s * 32 + g * 8 + t;
        const float* W = Wg + ((size_t)l * HEADS + head) * HID * FOUT;
        g_Wp2[idx] = make_float2(tf32r(W[(size_t)k * FOUT + d]),
                                 tf32r(W[(size_t)(k + 4) * FOUT + d]));
    } else if (bidx < K0_W2_BLKS + K0_W1_BLKS) {
        int idx = (bidx - K0_W2_BLKS) * 256 + threadIdx.x;   // [4][4][4][128][4]
        int t    = idx & 3;
        int c    = (idx >> 2) & 127;
        int g    = (idx >> 9) & 3;
        int s    = (idx >> 11) & 3;
        int tile = idx >> 13;
        int col  = tile * 128 + c;
        int k    = s * 32 + g * 8 + t;
        g_Wp1[idx] = make_float2(tf32r(Wm[(size_t)k * HID + col]),
                                 tf32r(Wm[(size_t)(k + 4) * HID + col]));
    } else {
        for (int c = threadIdx.x; c < HID; c += 256) {
            float s = 0.f;
#pragma unroll 8
            for (int k = 0; k < FIN; k++) s += tf32r(Wm[(size_t)k * HID + c]);
            g_cs[c] = s;
        }
    }
}

// ===========================================================================
// shared GEMM tile config — packed B
// ===========================================================================
#define TM 128
#define TN 128
#define KC 32
#define NBUF 3
#define A_STRIDE 36
#define A_BYTES (TM * A_STRIDE * 4)        // 18432
#define B_BYTES 16384
#define STAGE_BYTES (A_BYTES + B_BYTES)    // 34816
#define K2_SMEM (NBUF * STAGE_BYTES)       // 104448

__device__ __forceinline__ int slot3(int s) { return s - (s / 3) * 3; }

// ===========================================================================
// K1M (tf32 mma): h_x = s_row*(x @ Wm) + t_row*colsum(Wm) + b  (packed B)
// ===========================================================================
__global__ __launch_bounds__(256, 2) void k1_mma(
    const float* __restrict__ x,
    const float* __restrict__ gamma, const float* __restrict__ beta,
    const float* __restrict__ mean,  const float* __restrict__ var,
    const float* __restrict__ bm)
{
    extern __shared__ __align__(16) char smem[];
    const int NS_K = FIN / KC;   // 4
    const int tid  = threadIdx.x;
    const int lane = tid & 31;
    const int wid  = tid >> 5;
    const int wm   = wid & 3;
    const int wn   = wid >> 2;
    const int tile = blockIdx.x;
    const int n0   = tile * TN;
    const int row0 = blockIdx.y * TM;
    const uint32_t sbase = smem_u32(smem);

    auto issue_stage = [&](int s) {
        const int p = slot3(s);
        const float* Ag = x + (size_t)row0 * FIN + s * KC;
        const uint32_t Ad = sbase + p * STAGE_BYTES;
#pragma unroll
        for (int i = 0; i < 4; i++) {
            int idx = tid + i * 256;
            int r = idx >> 3, k4 = idx & 7;
            cp_async16(Ad + r * (A_STRIDE * 4) + k4 * 16,
                       Ag + (size_t)r * FIN + k4 * 4);
        }
        const uint32_t Bd = sbase + p * STAGE_BYTES + A_BYTES;
        const char* Bsrc = (const char*)(g_Wp1 + ((size_t)(tile * 4 + s)) * 2048);
#pragma unroll
        for (int i = 0; i < 4; i++) {
            int idx = tid + i * 256;
            cp_async16(Bd + idx * 16, Bsrc + idx * 16);
        }
    };

    float acc[2][8][4];
#pragma unroll
    for (int mt = 0; mt < 2; mt++)
#pragma unroll
        for (int nt = 0; nt < 8; nt++)
#pragma unroll
            for (int q = 0; q < 4; q++) acc[mt][nt][q] = 0.f;

#pragma unroll
    for (int s = 0; s < NBUF - 1; s++) { issue_stage(s); cp_commit(); }

#pragma unroll 1
    for (int s = 0; s < NS_K; s++) {
        if (s < NS_K - 1) cp_wait<1>();
        else              cp_wait<0>();
        __syncthreads();
        if (s + NBUF - 1 < NS_K) issue_stage(s + NBUF - 1);
        cp_commit();

        const float* As = (const float*)(smem + slot3(s) * STAGE_BYTES);
        const float2* Bp = (const float2*)((const char*)As + A_BYTES);

#pragma unroll
        for (int ks = 0; ks < KC / 8; ks++) {
            const int kb = ks * 8;
            uint32_t a[2][4], b[8][2];
#pragma unroll
            for (int mt = 0; mt < 2; mt++) {
                int r = wm * 32 + mt * 16 + (lane >> 2);
                int k = kb + (lane & 3);
                a[mt][0] = tf32u(As[r * A_STRIDE + k]);
                a[mt][1] = tf32u(As[(r + 8) * A_STRIDE + k]);
                a[mt][2] = tf32u(As[r * A_STRIDE + k + 4]);
                a[mt][3] = tf32u(As[(r + 8) * A_STRIDE + k + 4]);
            }
#pragma unroll
            for (int nt = 0; nt < 8; nt++) {
                int c = wn * 64 + nt * 8 + (lane >> 2);
                float2 v = Bp[(ks * 128 + c) * 4 + (lane & 3)];
                b[nt][0] = __float_as_uint(v.x);
                b[nt][1] = __float_as_uint(v.y);
            }
#pragma unroll
            for (int mt = 0; mt < 2; mt++)
#pragma unroll
                for (int nt = 0; nt < 8; nt++)
                    mma_tf32(acc[mt][nt], a[mt], b[nt]);
        }
    }

    const int rbase = wm * 32 + (lane >> 2);
    float sv[4], tv[4];
#pragma unroll
    for (int q = 0; q < 4; q++) {
        int r = row0 + rbase + q * 8;
        int n = r % NN;
        float sc = gamma[n] * rsqrtf(var[n] + 1e-5f);
        sv[q] = sc;
        tv[q] = beta[n] - mean[n] * sc;
    }
#pragma unroll
    for (int mt = 0; mt < 2; mt++) {
        int r = row0 + rbase + mt * 16;
#pragma unroll
        for (int nt = 0; nt < 8; nt++) {
            int c = n0 + wn * 64 + nt * 8 + 2 * (lane & 3);
            float cs0 = g_cs[c], cs1 = g_cs[c + 1];
            float b0 = bm[c], b1 = bm[c + 1];
            int q0 = mt * 2, q1 = mt * 2 + 1;
            *(float2*)&g_hx[(size_t)r * HID + c] = make_float2(
                tf32r(sv[q0] * acc[mt][nt][0] + tv[q0] * cs0 + b0),
                tf32r(sv[q0] * acc[mt][nt][1] + tv[q0] * cs1 + b1));
            *(float2*)&g_hx[(size_t)(r + 8) * HID + c] = make_float2(
                tf32r(sv[q1] * acc[mt][nt][2] + tv[q1] * cs0 + b0),
                tf32r(sv[q1] * acc[mt][nt][3] + tv[q1] * cs1 + b1));
        }
    }
}

// ===========================================================================
// K2 (tf32 mma, packed B): g_h = g_hx @ W_gat[l]
// ===========================================================================
__global__ __launch_bounds__(256, 2) void k2_mma(int layer)
{
    extern __shared__ __align__(16) char smem[];
    const int NS_K = HID / KC;   // 16
    const int tid  = threadIdx.x;
    const int lane = tid & 31;
    const int wid  = tid >> 5;
    const int wm   = wid & 3;
    const int wn   = wid >> 2;
    const int tile = blockIdx.x;
    const int n0   = tile * TN;
    const int row0 = blockIdx.y * TM;
    const uint32_t sbase = smem_u32(smem);
    const float2* Wp = g_Wp2 + ((size_t)(layer * 4 + tile) * 16) * 2048;

    auto issue_stage = [&](int s) {
        const int p = slot3(s);
        const float* Ag = g_hx + (size_t)row0 * HID + s * KC;
        const uint32_t Ad = sbase + p * STAGE_BYTES;
#pragma unroll
        for (int i = 0; i < 4; i++) {
            int idx = tid + i * 256;
            int r = idx >> 3, k4 = idx & 7;
            cp_async16(Ad + r * (A_STRIDE * 4) + k4 * 16,
                       Ag + (size_t)r * HID + k4 * 4);
        }
        const uint32_t Bd = sbase + p * STAGE_BYTES + A_BYTES;
        const char* Bsrc = (const char*)(Wp + (size_t)s * 2048);
#pragma unroll
        for (int i = 0; i < 4; i++) {
            int idx = tid + i * 256;
            cp_async16(Bd + idx * 16, Bsrc + idx * 16);
        }
    };

    float acc[2][8][4];
#pragma unroll
    for (int mt = 0; mt < 2; mt++)
#pragma unroll
        for (int nt = 0; nt < 8; nt++)
#pragma unroll
            for (int q = 0; q < 4; q++) acc[mt][nt][q] = 0.f;

#pragma unroll
    for (int s = 0; s < NBUF - 1; s++) { issue_stage(s); cp_commit(); }

#pragma unroll 1
    for (int s = 0; s < NS_K; s++) {
        if (s < NS_K - 1) cp_wait<1>();
        else              cp_wait<0>();
        __syncthreads();
        if (s + NBUF - 1 < NS_K) issue_stage(s + NBUF - 1);
        cp_commit();

        const float* As = (const float*)(smem + slot3(s) * STAGE_BYTES);
        const float2* Bp = (const float2*)((const char*)As + A_BYTES);

#pragma unroll
        for (int ks = 0; ks < KC / 8; ks++) {
            const int kb = ks * 8;
            uint32_t a[2][4], b[8][2];
#pragma unroll
            for (int mt = 0; mt < 2; mt++) {
                int r = wm * 32 + mt * 16 + (lane >> 2);
                int k = kb + (lane & 3);
                a[mt][0] = __float_as_uint(As[r * A_STRIDE + k]);
                a[mt][1] = __float_as_uint(As[(r + 8) * A_STRIDE + k]);
                a[mt][2] = __float_as_uint(As[r * A_STRIDE + k + 4]);
                a[mt][3] = __float_as_uint(As[(r + 8) * A_STRIDE + k + 4]);
            }
#pragma unroll
            for (int nt = 0; nt < 8; nt++) {
                int c = wn * 64 + nt * 8 + (lane >> 2);
                float2 v = Bp[(ks * 128 + c) * 4 + (lane & 3)];
                b[nt][0] = __float_as_uint(v.x);
                b[nt][1] = __float_as_uint(v.y);
            }
#pragma unroll
            for (int mt = 0; mt < 2; mt++)
#pragma unroll
                for (int nt = 0; nt < 8; nt++)
                    mma_tf32(acc[mt][nt], a[mt], b[nt]);
        }
    }

#pragma unroll
    for (int mt = 0; mt < 2; mt++) {
        int r = row0 + wm * 32 + mt * 16 + (lane >> 2);
#pragma unroll
        for (int nt = 0; nt < 8; nt++) {
            int c = n0 + wn * 64 + nt * 8 + 2 * (lane & 3);
            *(float2*)&g_h[(size_t)r * HID + c] =
                make_float2(acc[mt][nt][0], acc[mt][nt][1]);
            *(float2*)&g_h[(size_t)(r + 8) * HID + c] =
                make_float2(acc[mt][nt][2], acc[mt][nt][3]);
        }
    }
}

// ===========================================================================
// K4 (layers 0,1): per-b attention, 8-head loop, smem adj mask.
// exp pass fused with column sums (thread owns column j = tid&63).
// ===========================================================================
#define HS_STR 72
#define ES_STR 68

__global__ __launch_bounds__(256) void k4_attn(
    const int* __restrict__ adj, const float* __restrict__ a_l)
{
    __shared__ float hs[64][HS_STR];
    __shared__ float es[64][ES_STR];
    __shared__ unsigned char mask[64 * 64];
    __shared__ float asv[2 * FOUT];
    __shared__ float f1[64], f2[64];
    __shared__ float ps[4][64];
    __shared__ float rsv[64];

    const int b    = blockIdx.x;
    const int tid  = threadIdx.x;
    const int lane = tid & 31;
    const int wid  = tid >> 5;

    const int* adjb = adj + (size_t)b * NN * NN;
    for (int idx = tid; idx < 64 * 64; idx += 256) {
        int i = idx >> 6, j = idx & 63;
        mask[idx] = (i < NN && j < NN && adjb[i * NN + j] > 0) ? 1 : 0;
    }

    const float* hrow = &g_h[(size_t)b * NN * HID];
    float* orow = &g_hx[(size_t)b * NN * HID];

#pragma unroll 1
    for (int head = 0; head < HEADS; head++) {
        __syncthreads();

        const float* hbase = hrow + head * FOUT;
        for (int idx = tid; idx < 64 * 16; idx += 256) {
            int j = idx >> 4, d4 = idx & 15;
            float4 v = (j < NN) ? *(const float4*)(hbase + (size_t)j * HID + d4 * 4)
                                : make_float4(0.f, 0.f, 0.f, 0.f);
            *(float4*)&hs[j][d4 * 4] = v;
        }
        if (tid < 2 * FOUT) asv[tid] = a_l[head * 2 * FOUT + tid];
        __syncthreads();

        {
            int node = tid >> 2, t = tid & 3;
            float s1 = 0.f, s2 = 0.f;
#pragma unroll
            for (int dd = 0; dd < 16; dd++) {
                int d = t * 16 + dd;
                float v = hs[node][d];
                s1 += v * asv[d];
                s2 += v * asv[FOUT + d];
            }
            s1 += __shfl_xor_sync(0xffffffffu, s1, 1);
            s1 += __shfl_xor_sync(0xffffffffu, s1, 2);
            s2 += __shfl_xor_sync(0xffffffffu, s2, 1);
            s2 += __shfl_xor_sync(0xffffffffu, s2, 2);
            if (t == 0) { f1[node] = s1; f2[node] = s2; }
        }
        __syncthreads();

        // fused: es write + column partial sums (thread owns column j)
        {
            int q = tid >> 6, j = tid & 63;
            float f1j = f1[j];
            float ssum = 0.f;
#pragma unroll
            for (int k = 0; k < 16; k++) {
                int i = q + k * 4;
                float e = 0.f;
                if (mask[i * 64 + j]) {
                    float v = f2[i] + f1j;
                    v = v > 0.f ? v : 0.2f * v;
                    e = tf32r(__expf(v));
                }
                es[i][j] = e;
                ssum += e;
            }
            ps[q][j] = ssum;
        }
        __syncthreads();
        if (tid < 64) {
            float s = ps[0][tid] + ps[1][tid] + ps[2][tid] + ps[3][tid];
            rsv[tid] = (s > 0.f) ? 1.f / s : 0.f;
        }
        __syncthreads();

        for (int idx = tid; idx < 64 * 16; idx += 256) {
            int j = idx >> 4, d4 = idx & 15;
            float rs = rsv[j];
            float4 v = *(float4*)&hs[j][d4 * 4];
            v.x = tf32r(v.x * rs); v.y = tf32r(v.y * rs);
            v.z = tf32r(v.z * rs); v.w = tf32r(v.w * rs);
            *(float4*)&hs[j][d4 * 4] = v;
        }
        __syncthreads();

        {
            const int wm = wid & 3, wn = wid >> 2;
            float acc[4][4];
#pragma unroll
            for (int nt = 0; nt < 4; nt++)
#pragma unroll
                for (int q = 0; q < 4; q++) acc[nt][q] = 0.f;

            const int r = wm * 16 + (lane >> 2);
#pragma unroll
            for (int kb = 0; kb < 64; kb += 8) {
                const int k = kb + (lane & 3);
                uint32_t a[4];
                a[0] = __float_as_uint(es[r][k]);
                a[1] = __float_as_uint(es[r + 8][k]);
                a[2] = __float_as_uint(es[r][k + 4]);
                a[3] = __float_as_uint(es[r + 8][k + 4]);
#pragma unroll
                for (int nt = 0; nt < 4; nt++) {
                    const int c = wn * 32 + nt * 8 + (lane >> 2);
                    uint32_t bb[2];
                    bb[0] = __float_as_uint(hs[k][c]);
                    bb[1] = __float_as_uint(hs[k + 4][c]);
                    mma_tf32(acc[nt], a, bb);
                }
            }

            const int i0 = wm * 16 + (lane >> 2);
            const int i1 = i0 + 8;
            float* ob = orow + head * FOUT;
#pragma unroll
            for (int nt = 0; nt < 4; nt++) {
                int c = wn * 32 + nt * 8 + 2 * (lane & 3);
                float v0 = acc[nt][0], v1 = acc[nt][1];
                v0 = v0 > 0.f ? v0 : expm1f(v0);
                v1 = v1 > 0.f ? v1 : expm1f(v1);
                *(float2*)(ob + (size_t)i0 * HID + c) =
                    make_float2(tf32r(v0), tf32r(v1));
                if (i1 < NN) {
                    float v2 = acc[nt][2], v3 = acc[nt][3];
                    v2 = v2 > 0.f ? v2 : expm1f(v2);
                    v3 = v3 > 0.f ? v3 : expm1f(v3);
                    *(float2*)(ob + (size_t)i1 * HID + c) =
                        make_float2(tf32r(v2), tf32r(v3));
                }
            }
        }
    }
}

// ===========================================================================
// K4_LAST (layer 2): same body, ELU output pooled in-block + W_out head
// + log_softmax. Fused exp+colsum as above.
// ===========================================================================
__global__ __launch_bounds__(256) void k4_last(
    const int* __restrict__ adj, const float* __restrict__ a_l,
    const float* __restrict__ Wout, const float* __restrict__ bout,
    float* __restrict__ out)
{
    __shared__ float hs[64][HS_STR];
    __shared__ float es[64][ES_STR];
    __shared__ unsigned char mask[64 * 64];
    __shared__ float asv[2 * FOUT];
    __shared__ float f1[64], f2[64];
    __shared__ float ps[4][64];
    __shared__ float rsv[64];
    __shared__ float pooled[HID];

    const int b    = blockIdx.x;
    const int tid  = threadIdx.x;
    const int lane = tid & 31;
    const int wid  = tid >> 5;

    const int* adjb = adj + (size_t)b * NN * NN;
    for (int idx = tid; idx < 64 * 64; idx += 256) {
        int i = idx >> 6, j = idx & 63;
        mask[idx] = (i < NN && j < NN && adjb[i * NN + j] > 0) ? 1 : 0;
    }
    pooled[tid] = 0.f;
    pooled[tid + 256] = 0.f;

    const float* hrow = &g_h[(size_t)b * NN * HID];

#pragma unroll 1
    for (int head = 0; head < HEADS; head++) {
        __syncthreads();

        const float* hbase = hrow + head * FOUT;
        for (int idx = tid; idx < 64 * 16; idx += 256) {
            int j = idx >> 4, d4 = idx & 15;
            float4 v = (j < NN) ? *(const float4*)(hbase + (size_t)j * HID + d4 * 4)
                                : make_float4(0.f, 0.f, 0.f, 0.f);
            *(float4*)&hs[j][d4 * 4] = v;
        }
        if (tid < 2 * FOUT) asv[tid] = a_l[head * 2 * FOUT + tid];
        __syncthreads();

        {
            int node = tid >> 2, t = tid & 3;
            float s1 = 0.f, s2 = 0.f;
#pragma unroll
            for (int dd = 0; dd < 16; dd++) {
                int d = t * 16 + dd;
                float v = hs[node][d];
                s1 += v * asv[d];
                s2 += v * asv[FOUT + d];
            }
            s1 += __shfl_xor_sync(0xffffffffu, s1, 1);
            s1 += __shfl_xor_sync(0xffffffffu, s1, 2);
            s2 += __shfl_xor_sync(0xffffffffu, s2, 1);
            s2 += __shfl_xor_sync(0xffffffffu, s2, 2);
            if (t == 0) { f1[node] = s1; f2[node] = s2; }
        }
        __syncthreads();

        {
            int q = tid >> 6, j = tid & 63;
            float f1j = f1[j];
            float ssum = 0.f;
#pragma unroll
            for (int k = 0; k < 16; k++) {
                int i = q + k * 4;
                float e = 0.f;
                if (mask[i * 64 + j]) {
                    float v = f2[i] + f1j;
                    v = v > 0.f ? v : 0.2f * v;
                    e = tf32r(__expf(v));
                }
                es[i][j] = e;
                ssum += e;
            }
            ps[q][j] = ssum;
        }
        __syncthreads();
        if (tid < 64) {
            float s = ps[0][tid] + ps[1][tid] + ps[2][tid] + ps[3][tid];
            rsv[tid] = (s > 0.f) ? 1.f / s : 0.f;
        }
        __syncthreads();

        for (int idx = tid; idx < 64 * 16; idx += 256) {
            int j = idx >> 4, d4 = idx & 15;
            float rs = rsv[j];
            float4 v = *(float4*)&hs[j][d4 * 4];
            v.x = tf32r(v.x * rs); v.y = tf32r(v.y * rs);
            v.z = tf32r(v.z * rs); v.w = tf32r(v.w * rs);
            *(float4*)&hs[j][d4 * 4] = v;
        }
        __syncthreads();

        {
            const int wm = wid & 3, wn = wid >> 2;
            float acc[4][4];
#pragma unroll
            for (int nt = 0; nt < 4; nt++)
#pragma unroll
                for (int q = 0; q < 4; q++) acc[nt][q] = 0.f;

            const int r = wm * 16 + (lane >> 2);
#pragma unroll
            for (int kb = 0; kb < 64; kb += 8) {
                const int k = kb + (lane & 3);
                uint32_t a[4];
                a[0] = __float_as_uint(es[r][k]);
                a[1] = __float_as_uint(es[r + 8][k]);
                a[2] = __float_as_uint(es[r][k + 4]);
                a[3] = __float_as_uint(es[r + 8][k + 4]);
#pragma unroll
                for (int nt = 0; nt < 4; nt++) {
                    const int c = wn * 32 + nt * 8 + (lane >> 2);
                    uint32_t bb[2];
                    bb[0] = __float_as_uint(hs[k][c]);
                    bb[1] = __float_as_uint(hs[k + 4][c]);
                    mma_tf32(acc[nt], a, bb);
                }
            }

            const int i0 = wm * 16 + (lane >> 2);
            const int i1 = i0 + 8;
            __syncthreads();   // all MMA hs reads done
#pragma unroll
            for (int nt = 0; nt < 4; nt++) {
                int c = wn * 32 + nt * 8 + 2 * (lane & 3);
                float v0 = acc[nt][0], v1 = acc[nt][1];
                float v2 = acc[nt][2], v3 = acc[nt][3];
                v0 = v0 > 0.f ? v0 : expm1f(v0);
                v1 = v1 > 0.f ? v1 : expm1f(v1);
                v2 = v2 > 0.f ? v2 : expm1f(v2);
                v3 = v3 > 0.f ? v3 : expm1f(v3);
                *(float2*)&hs[i0][c] = make_float2(v0, v1);
                *(float2*)&hs[i1][c] = make_float2(v2, v3);
            }
            __syncthreads();
            {
                int q = tid >> 6, c = tid & 63;
                float s = 0.f;
#pragma unroll
                for (int k = 0; k < 16; k++) s += hs[q + k * 4][c];
                ps[q][c] = s;
            }
            __syncthreads();
            if (tid < 64)
                pooled[head * FOUT + tid] +=
                    ps[0][tid] + ps[1][tid] + ps[2][tid] + ps[3][tid];
        }
    }

    __syncthreads();
    float l0 = 0.f, l1 = 0.f, l2 = 0.f;
#pragma unroll
    for (int c = tid; c < HID; c += 256) {
        float p = pooled[c];
        l0 += p * Wout[c * 3 + 0];
        l1 += p * Wout[c * 3 + 1];
        l2 += p * Wout[c * 3 + 2];
    }
#pragma unroll
    for (int off = 16; off > 0; off >>= 1) {
        l0 += __shfl_down_sync(0xffffffffu, l0, off);
        l1 += __shfl_down_sync(0xffffffffu, l1, off);
        l2 += __shfl_down_sync(0xffffffffu, l2, off);
    }
    if (lane == 0) { ps[0][wid] = l0; ps[1][wid] = l1; ps[2][wid] = l2; }
    __syncthreads();
    if (tid == 0) {
        float lg[3];
#pragma unroll
        for (int c = 0; c < 3; c++) {
            float t = 0.f;
#pragma unroll
            for (int w = 0; w < 8; w++) t += ps[c][w];
            lg[c] = t + bout[c];
        }
        float m = fmaxf(lg[0], fmaxf(lg[1], lg[2]));
        float sum = expf(lg[0] - m) + expf(lg[1] - m) + expf(lg[2] - m);
        float lse = logf(sum) + m;
        out[b * 3 + 0] = lg[0] - lse;
        out[b * 3 + 1] = lg[1] - lse;
        out[b * 3 + 2] = lg[2] - lse;
    }
}

// ===========================================================================
extern "C" void kernel_launch(void* const* d_in, const int* in_sizes, int n_in,
                              void* d_out, int out_size)
{
    const float* x     = (const float*)d_in[0];
    const int*   adj   = (const int*)  d_in[1];
    const float* gamma = (const float*)d_in[2];
    const float* beta  = (const float*)d_in[3];
    const float* mean  = (const float*)d_in[4];
    const float* var   = (const float*)d_in[5];
    const float* Wm    = (const float*)d_in[6];
    const float* bm    = (const float*)d_in[7];
    const float* Wg    = (const float*)d_in[8];
    const float* ag    = (const float*)d_in[9];
    const float* Wo    = (const float*)d_in[10];
    const float* bo    = (const float*)d_in[11];
    float* out = (float*)d_out;

    cudaFuncSetAttribute(k2_mma, cudaFuncAttributeMaxDynamicSharedMemorySize, K2_SMEM);
    cudaFuncSetAttribute(k1_mma, cudaFuncAttributeMaxDynamicSharedMemorySize, K2_SMEM);

    k0_all<<<K0_W2_BLKS + K0_W1_BLKS + 1, 256>>>(Wg, Wm);

    k1_mma<<<dim3(HID / TN, NROWS / TM), 256, K2_SMEM>>>(x, gamma, beta, mean, var, bm);

    for (int l = 0; l < 2; l++) {
        k2_mma<<<dim3(HID / TN, NROWS / TM), 256, K2_SMEM>>>(l);
        k4_attn<<<BB, 256>>>(adj, ag + (size_t)l * HEADS * 2 * FOUT);
    }
    k2_mma<<<dim3(HID / TN, NROWS / TM), 256, K2_SMEM>>>(2);
    k4_last<<<BB, 256>>>(adj, ag + (size_t)2 * HEADS * 2 * FOUT, Wo, bo, out);
}